// round 11
// baseline (speedup 1.0000x reference)
#include <cuda_runtime.h>
#include <math.h>

#define Bz 32
#define Tz 512
#define Iz 256
#define Hz 1024
#define G4 4096
#define Oz 512
#define TR 500

typedef unsigned long long ull;

// ---- packed f32x2 helpers (sm_103a) ----
__device__ __forceinline__ ull pack2(float x, float y) {
    ull r; asm("mov.b64 %0, {%1,%2};" : "=l"(r) : "f"(x), "f"(y)); return r;
}
__device__ __forceinline__ void unpack2(ull v, float& x, float& y) {
    asm("mov.b64 {%0,%1}, %2;" : "=f"(x), "=f"(y) : "l"(v));
}
__device__ __forceinline__ void fma2(ull& d, ull a, ull b) {
    asm("fma.rn.f32x2 %0, %1, %2, %0;" : "+l"(d) : "l"(a), "l"(b));
}
__device__ __forceinline__ ull add2(ull a, ull b) {
    ull r; asm("add.rn.f32x2 %0, %1, %2;" : "=l"(r) : "l"(a), "l"(b)); return r;
}

__device__ __forceinline__ float sig_f(float x) {
    return __fdividef(1.0f, 1.0f + __expf(-x));
}
__device__ __forceinline__ float tanh_f(float x) {
    return 1.0f - __fdividef(2.0f, __expf(2.0f * x) + 1.0f);
}

// cp.async 16B: global -> shared, L2-only path
__device__ __forceinline__ void cp16(unsigned smem_addr, const void* gptr) {
    asm volatile("cp.async.cg.shared.global [%0], [%1], 16;"
                 :: "r"(smem_addr), "l"(gptr) : "memory");
}

// ---- scratch (device globals: allocation-free) ----
__device__ __align__(16) float g_xt[Tz * Bz * Iz];
__device__ __align__(16) float g_xg[Tz * Bz * G4];
__device__ __align__(16) float g_h1[Tz * Bz * Hz];
__device__ __align__(16) float g_h2[Tz * Bz * Hz];

// ---- software grid barrier (128 blocks, all co-resident: 1 block/SM) ----
__device__ unsigned g_bar_count = 0;
__device__ volatile unsigned g_bar_gen = 0;

__device__ __forceinline__ void grid_sync() {
    __syncthreads();
    if (threadIdx.x == 0) {
        __threadfence();
        unsigned gen = g_bar_gen;
        if (atomicAdd(&g_bar_count, 1u) == gridDim.x - 1u) {
            g_bar_count = 0;
            __threadfence();
            g_bar_gen = gen + 1u;
        } else {
            while (g_bar_gen == gen) { }
            __threadfence();
        }
    }
    __syncthreads();
}

// ---------------------------------------------------------------------------
// Transpose x: [B,T,I] -> time-major [T,B,I] (float4)
// ---------------------------------------------------------------------------
__global__ void transpose_x(const float4* __restrict__ x, float4* __restrict__ xt) {
    int idx = blockIdx.x * blockDim.x + threadIdx.x;   // < 1048576
    int i4 = idx & 63;
    int m  = idx >> 6;
    int t  = m >> 5;
    int b  = m & 31;
    xt[idx] = x[(b * Tz + t) * (Iz / 4) + i4];
}

// ---------------------------------------------------------------------------
// SGEMM (TN): unchanged from R9 (passing; fma ~59%)
// ---------------------------------------------------------------------------
template <int MODE>
__global__ __launch_bounds__(256, 2)
void sgemm_tn(const float* __restrict__ A, const float* __restrict__ W,
              const float* __restrict__ b1, const float* __restrict__ b2,
              float* __restrict__ C, int M, int N, int K) {
    __shared__ __align__(16) float As[16][128];
    __shared__ __align__(16) float Bs[16][128];

    const int tid = threadIdx.x;
    const int ty = tid >> 4, tx = tid & 15;
    const int m0 = blockIdx.y * 128, n0 = blockIdx.x * 128;

    ull acc[4][8];
#pragma unroll
    for (int i = 0; i < 4; i++)
#pragma unroll
        for (int j = 0; j < 8; j++) acc[i][j] = 0ULL;

    const float* arow[2];
    int arr[2], acc4[2];
#pragma unroll
    for (int i = 0; i < 2; i++) {
        int item = tid + 256 * i;
        int r = item >> 2, c4 = item & 3;
        arr[i] = r; acc4[i] = c4;
        int m = m0 + r;
        if (MODE == 1) {
            int bb = m / TR, t = m - bb * TR;
            arow[i] = A + (long long)(t * Bz + bb) * K;
        } else {
            arow[i] = A + (long long)m * K;
        }
    }
    const float* wrow[2];
#pragma unroll
    for (int i = 0; i < 2; i++) wrow[i] = W + (long long)(n0 + arr[i]) * K;

    float4 va[2], vb[2];
#pragma unroll
    for (int i = 0; i < 2; i++) {
        va[i] = *(const float4*)(arow[i] + acc4[i] * 4);
        vb[i] = *(const float4*)(wrow[i] + acc4[i] * 4);
    }
#pragma unroll
    for (int i = 0; i < 2; i++) {
        int r = arr[i], c4 = acc4[i];
        As[c4 * 4 + 0][r] = va[i].x; As[c4 * 4 + 1][r] = va[i].y;
        As[c4 * 4 + 2][r] = va[i].z; As[c4 * 4 + 3][r] = va[i].w;
        Bs[c4 * 4 + 0][r] = vb[i].x; Bs[c4 * 4 + 1][r] = vb[i].y;
        Bs[c4 * 4 + 2][r] = vb[i].z; Bs[c4 * 4 + 3][r] = vb[i].w;
    }
    __syncthreads();

    const int KT = K >> 4;
    for (int kt = 0; kt < KT; kt++) {
        if (kt + 1 < KT) {
            int k0n = (kt + 1) << 4;
#pragma unroll
            for (int i = 0; i < 2; i++) {
                va[i] = *(const float4*)(arow[i] + k0n + acc4[i] * 4);
                vb[i] = *(const float4*)(wrow[i] + k0n + acc4[i] * 4);
            }
        }
#pragma unroll
        for (int k = 0; k < 16; k++) {
            ull a2[4];
#pragma unroll
            for (int mp = 0; mp < 4; mp++)
                a2[mp] = *(const ull*)&As[k][ty * 8 + mp * 2];
            float4 bv0 = *(const float4*)&Bs[k][tx * 8];
            float4 bv1 = *(const float4*)&Bs[k][tx * 8 + 4];
            ull bd[8];
            bd[0] = pack2(bv0.x, bv0.x); bd[1] = pack2(bv0.y, bv0.y);
            bd[2] = pack2(bv0.z, bv0.z); bd[3] = pack2(bv0.w, bv0.w);
            bd[4] = pack2(bv1.x, bv1.x); bd[5] = pack2(bv1.y, bv1.y);
            bd[6] = pack2(bv1.z, bv1.z); bd[7] = pack2(bv1.w, bv1.w);
#pragma unroll
            for (int mp = 0; mp < 4; mp++)
#pragma unroll
                for (int n = 0; n < 8; n++) fma2(acc[mp][n], a2[mp], bd[n]);
        }
        if (kt + 1 < KT) {
            __syncthreads();
#pragma unroll
            for (int i = 0; i < 2; i++) {
                int r = arr[i], c4 = acc4[i];
                As[c4 * 4 + 0][r] = va[i].x; As[c4 * 4 + 1][r] = va[i].y;
                As[c4 * 4 + 2][r] = va[i].z; As[c4 * 4 + 3][r] = va[i].w;
                Bs[c4 * 4 + 0][r] = vb[i].x; Bs[c4 * 4 + 1][r] = vb[i].y;
                Bs[c4 * 4 + 2][r] = vb[i].z; Bs[c4 * 4 + 3][r] = vb[i].w;
            }
            __syncthreads();
        }
    }

    float bb[8];
#pragma unroll
    for (int n = 0; n < 8; n++) {
        int col = n0 + tx * 8 + n;
        bb[n] = b1[col] + (b2 ? b2[col] : 0.0f);
    }
#pragma unroll
    for (int mp = 0; mp < 4; mp++) {
        float lo[8], hi[8];
#pragma unroll
        for (int n = 0; n < 8; n++) unpack2(acc[mp][n], lo[n], hi[n]);
        int row0 = m0 + ty * 8 + mp * 2;
        float* c0 = C + (long long)row0 * N + n0 + tx * 8;
        float* c1 = c0 + N;
        float o0[8], o1[8];
#pragma unroll
        for (int n = 0; n < 8; n++) { o0[n] = lo[n] + bb[n]; o1[n] = hi[n] + bb[n]; }
        *(float4*)(c0)     = make_float4(o0[0], o0[1], o0[2], o0[3]);
        *(float4*)(c0 + 4) = make_float4(o0[4], o0[5], o0[6], o0[7]);
        *(float4*)(c1)     = make_float4(o1[0], o1[1], o1[2], o1[3]);
        *(float4*)(c1 + 4) = make_float4(o1[4], o1[5], o1[6], o1[7]);
    }
}

// ---------------------------------------------------------------------------
// Persistent LSTM recurrence, R10: split-k + dual interleaved rings.
// 128 blocks x 512 threads (16 warps). Warps u and u+8 both own hidden unit
// j = 8*blk + (u&7); warp half w = u>>3 covers k in [512w, 512w+512).
// Lane k-slice: {512w + 128m + 4*lane .. +3, m=0..3} -> 32 ull weight regs.
// Two rings rotate by 2 lanes (A adds batch lane+2s, B adds lane+2s+1): two
// independent 16-hop serial chains instead of one 32-hop chain; B re-aligned
// by one lane at the end. Cross-warp (k-half) combine via a 4KB smem exchange.
// 4 warps/SMSP doubles latency hiding vs R9's 2.
// ---------------------------------------------------------------------------
__global__ __launch_bounds__(512, 1)
void lstm_recurrence(const float* __restrict__ xg,   // [T][B][4H]
                     const float* __restrict__ Whh,  // [4H][H]
                     float* __restrict__ hout) {     // [T][B][H]
    extern __shared__ float sh[];                    // h: [32][1024] = 128KB, +4KB reduce
    ull* red = (ull*)(sh + Bz * Hz);                 // [8][32][2] ull
    const int tid = threadIdx.x;
    const int lane = tid & 31;
    const int uw = tid >> 5;          // 0..15
    const int u = uw & 7;             // unit-in-block
    const int w = uw >> 3;            // k-half
    const int j = blockIdx.x * 8 + u;

    unsigned sh_u32;
    asm("{ .reg .u64 t0; cvta.to.shared.u64 t0, %1; cvt.u32.u64 %0, t0; }"
        : "=r"(sh_u32) : "l"(sh));

    // Weights: per gate 8 ull over this warp's k-half
    ull wi[8], wf[8], wg[8], wo[8];
    {
        const ulonglong2* Wi = (const ulonglong2*)(Whh + (size_t)j * Hz + 512 * w) + lane;
        const ulonglong2* Wf = (const ulonglong2*)(Whh + (size_t)(Hz + j) * Hz + 512 * w) + lane;
        const ulonglong2* Wg = (const ulonglong2*)(Whh + (size_t)(2 * Hz + j) * Hz + 512 * w) + lane;
        const ulonglong2* Wo = (const ulonglong2*)(Whh + (size_t)(3 * Hz + j) * Hz + 512 * w) + lane;
#pragma unroll
        for (int m = 0; m < 4; m++) {
            ulonglong2 a = Wi[32 * m]; wi[2 * m] = a.x; wi[2 * m + 1] = a.y;
            ulonglong2 b = Wf[32 * m]; wf[2 * m] = b.x; wf[2 * m + 1] = b.y;
            ulonglong2 c = Wg[32 * m]; wg[2 * m] = c.x; wg[2 * m + 1] = c.y;
            ulonglong2 d = Wo[32 * m]; wo[2 * m] = d.x; wo[2 * m + 1] = d.y;
        }
    }

    const float* shw = sh + 512 * w;  // this warp's k-half within each batch row
    const int rot2 = (lane + 2) & 31;
    const int up1  = (lane + 31) & 31;
    float creg = 0.0f;                // valid in lower warps (w==0) only

    for (int t = 0; t < Tz; t++) {
        float xi = 0.f, xf = 0.f, xgv = 0.f, xo = 0.f;
        if (w == 0) {
            const float* xr = xg + (size_t)t * Bz * G4 + (size_t)lane * G4;
            xi  = __ldg(xr + j);
            xf  = __ldg(xr + Hz + j);
            xgv = __ldg(xr + 2 * Hz + j);
            xo  = __ldg(xr + 3 * Hz + j);
        }

        if (t > 0) {
            const float* hp = hout + (size_t)(t - 1) * Bz * Hz;
#pragma unroll
            for (int i = 0; i < 16; i++) {
                int idx = tid + 512 * i;
                cp16(sh_u32 + (unsigned)idx * 16u, hp + (size_t)idx * 4);
            }
            asm volatile("cp.async.commit_group;" ::: "memory");
            asm volatile("cp.async.wait_group 0;" ::: "memory");
        }
        __syncthreads();   // h staged (all warps wrote parts of it)

        ull t01 = 0ULL, t23 = 0ULL;
        if (t > 0) {
            ull A01 = 0, A23 = 0, B01 = 0, B23 = 0;
#pragma unroll 1
            for (int s = 0; s < 16; s++) {
                {   // ring A: batch (lane + 2s)
                    const int b = (lane + 2 * s) & 31;
                    const ulonglong2* hb = (const ulonglong2*)(shw + b * Hz) + lane;
                    ull ai = 0, af = 0, ag = 0, ao = 0;
#pragma unroll
                    for (int m = 0; m < 4; m++) {
                        ulonglong2 h2 = hb[32 * m];
                        fma2(ai, h2.x, wi[2 * m]);     fma2(af, h2.x, wf[2 * m]);
                        fma2(ag, h2.x, wg[2 * m]);     fma2(ao, h2.x, wo[2 * m]);
                        fma2(ai, h2.y, wi[2 * m + 1]); fma2(af, h2.y, wf[2 * m + 1]);
                        fma2(ag, h2.y, wg[2 * m + 1]); fma2(ao, h2.y, wo[2 * m + 1]);
                    }
                    float l0, h0;
                    unpack2(ai, l0, h0); float iv = l0 + h0;
                    unpack2(af, l0, h0); float fv = l0 + h0;
                    unpack2(ag, l0, h0); float gv = l0 + h0;
                    unpack2(ao, l0, h0); float ov = l0 + h0;
                    A01 = add2(A01, pack2(iv, fv));
                    A23 = add2(A23, pack2(gv, ov));
                    A01 = __shfl_sync(0xffffffffu, A01, rot2);
                    A23 = __shfl_sync(0xffffffffu, A23, rot2);
                }
                {   // ring B: batch (lane + 2s + 1)
                    const int b = (lane + 2 * s + 1) & 31;
                    const ulonglong2* hb = (const ulonglong2*)(shw + b * Hz) + lane;
                    ull ai = 0, af = 0, ag = 0, ao = 0;
#pragma unroll
                    for (int m = 0; m < 4; m++) {
                        ulonglong2 h2 = hb[32 * m];
                        fma2(ai, h2.x, wi[2 * m]);     fma2(af, h2.x, wf[2 * m]);
                        fma2(ag, h2.x, wg[2 * m]);     fma2(ao, h2.x, wo[2 * m]);
                        fma2(ai, h2.y, wi[2 * m + 1]); fma2(af, h2.y, wf[2 * m + 1]);
                        fma2(ag, h2.y, wg[2 * m + 1]); fma2(ao, h2.y, wo[2 * m + 1]);
                    }
                    float l0, h0;
                    unpack2(ai, l0, h0); float iv = l0 + h0;
                    unpack2(af, l0, h0); float fv = l0 + h0;
                    unpack2(ag, l0, h0); float gv = l0 + h0;
                    unpack2(ao, l0, h0); float ov = l0 + h0;
                    B01 = add2(B01, pack2(iv, fv));
                    B23 = add2(B23, pack2(gv, ov));
                    B01 = __shfl_sync(0xffffffffu, B01, rot2);
                    B23 = __shfl_sync(0xffffffffu, B23, rot2);
                }
            }
            // align ring B (acc for batch b sits on lane b-1): shift up by 1
            B01 = __shfl_sync(0xffffffffu, B01, up1);
            B23 = __shfl_sync(0xffffffffu, B23, up1);
            t01 = add2(A01, B01);
            t23 = add2(A23, B23);
        }

        // upper warps publish their k-half partials
        if (w == 1) {
            ulonglong2 v; v.x = t01; v.y = t23;
            *((ulonglong2*)&red[(u * 32 + lane) * 2]) = v;
        }
        __syncthreads();   // red ready

        if (w == 0) {
            if (t > 0) {
                ulonglong2 v = *((const ulonglong2*)&red[(u * 32 + lane) * 2]);
                t01 = add2(t01, v.x);
                t23 = add2(t23, v.y);
            }
            float pi, pf, pg, po;
            unpack2(t01, pi, pf);
            unpack2(t23, pg, po);
            pi += xi; pf += xf; pg += xgv; po += xo;

            float si = sig_f(pi);
            float sf = sig_f(pf);
            float so = sig_f(po);
            creg = sf * creg + si * tanh_f(pg);
            float hn = so * tanh_f(creg);
            hout[(size_t)t * Bz * Hz + (size_t)lane * Hz + j] = hn;
        }

        grid_sync();
    }
}

// ---------------------------------------------------------------------------
extern "C" void kernel_launch(void* const* d_in, const int* in_sizes, int n_in,
                              void* d_out, int out_size) {
    (void)in_sizes; (void)n_in; (void)out_size;
    const float* x     = (const float*)d_in[0];
    const float* W_ih0 = (const float*)d_in[1];
    const float* W_hh0 = (const float*)d_in[2];
    const float* b_ih0 = (const float*)d_in[3];
    const float* b_hh0 = (const float*)d_in[4];
    const float* W_ih1 = (const float*)d_in[5];
    const float* W_hh1 = (const float*)d_in[6];
    const float* b_ih1 = (const float*)d_in[7];
    const float* b_hh1 = (const float*)d_in[8];
    const float* W_fc  = (const float*)d_in[9];
    const float* b_fc  = (const float*)d_in[10];
    float* out = (float*)d_out;

    float *xt, *xgp, *h1, *h2;
    cudaGetSymbolAddress((void**)&xt, g_xt);
    cudaGetSymbolAddress((void**)&xgp, g_xg);
    cudaGetSymbolAddress((void**)&h1, g_h1);
    cudaGetSymbolAddress((void**)&h2, g_h2);

    const int REC_SMEM = (Bz * Hz + 8 * 32 * 4) * (int)sizeof(float);  // 128KB + 4KB
    cudaFuncSetAttribute(lstm_recurrence,
                         cudaFuncAttributeMaxDynamicSharedMemorySize, REC_SMEM);

    // x -> time-major
    transpose_x<<<4096, 256>>>((const float4*)x, (float4*)xt);

    // layer 0: input GEMM + persistent recurrence
    sgemm_tn<0><<<dim3(G4 / 128, (Tz * Bz) / 128), 256>>>(xt, W_ih0, b_ih0, b_hh0,
                                                          xgp, Tz * Bz, G4, Iz);
    lstm_recurrence<<<128, 512, REC_SMEM>>>(xgp, W_hh0, h1);

    // layer 1: input GEMM + persistent recurrence
    sgemm_tn<0><<<dim3(G4 / 128, (Tz * Bz) / 128), 256>>>(h1, W_ih1, b_ih1, b_hh1,
                                                          xgp, Tz * Bz, G4, Hz);
    lstm_recurrence<<<128, 512, REC_SMEM>>>(xgp, W_hh1, h2);

    // FC over truncated sequence: out[b,t,o], m = b*500 + t -> [16000,512]
    sgemm_tn<1><<<dim3(Oz / 128, (Bz * TR) / 128), 256>>>(h2, W_fc, b_fc, nullptr,
                                                          out, Bz * TR, Oz, Hz);
}

// round 13
// speedup vs baseline: 1.2951x; 1.2951x over previous
#include <cuda_runtime.h>
#include <math.h>

#define Bz 32
#define Tz 512
#define Iz 256
#define Hz 1024
#define G4 4096
#define Oz 512
#define TR 500

typedef unsigned long long ull;

// ---- packed f32x2 helpers (sm_103a) ----
__device__ __forceinline__ ull pack2(float x, float y) {
    ull r; asm("mov.b64 %0, {%1,%2};" : "=l"(r) : "f"(x), "f"(y)); return r;
}
__device__ __forceinline__ void unpack2(ull v, float& x, float& y) {
    asm("mov.b64 {%0,%1}, %2;" : "=f"(x), "=f"(y) : "l"(v));
}
__device__ __forceinline__ void fma2(ull& d, ull a, ull b) {
    asm("fma.rn.f32x2 %0, %1, %2, %0;" : "+l"(d) : "l"(a), "l"(b));
}
__device__ __forceinline__ ull add2(ull a, ull b) {
    ull r; asm("add.rn.f32x2 %0, %1, %2;" : "=l"(r) : "l"(a), "l"(b)); return r;
}

__device__ __forceinline__ float sig_f(float x) {
    return __fdividef(1.0f, 1.0f + __expf(-x));
}
__device__ __forceinline__ float tanh_f(float x) {
    return 1.0f - __fdividef(2.0f, __expf(2.0f * x) + 1.0f);
}

// round-to-nearest tf32 (low 13 mantissa bits zeroed, rna)
__device__ __forceinline__ float t32(float x) {
    unsigned u; asm("cvt.rna.tf32.f32 %0, %1;" : "=r"(u) : "f"(x));
    return __uint_as_float(u);
}

// cp.async 16B: global -> shared
__device__ __forceinline__ void cp16(unsigned smem_addr, const void* gptr) {
    asm volatile("cp.async.cg.shared.global [%0], [%1], 16;"
                 :: "r"(smem_addr), "l"(gptr) : "memory");
}

// mma.sync m16n8k8 tf32: D += A*B (accumulate in-place)
__device__ __forceinline__ void mma_tf32(float* c, const float* a, const float* b) {
    asm volatile(
        "mma.sync.aligned.m16n8k8.row.col.f32.tf32.tf32.f32 "
        "{%0,%1,%2,%3}, {%4,%5,%6,%7}, {%8,%9}, {%0,%1,%2,%3};"
        : "+f"(c[0]), "+f"(c[1]), "+f"(c[2]), "+f"(c[3])
        : "r"(__float_as_uint(a[0])), "r"(__float_as_uint(a[1])),
          "r"(__float_as_uint(a[2])), "r"(__float_as_uint(a[3])),
          "r"(__float_as_uint(b[0])), "r"(__float_as_uint(b[1])));
}

// ---- scratch (device globals: allocation-free) ----
__device__ __align__(16) float g_xt [Tz * Bz * Iz];    // tf32-rounded x, time-major
__device__ __align__(16) float g_xg [Tz * Bz * G4];
__device__ __align__(16) float g_h1 [Tz * Bz * Hz];
__device__ __align__(16) float g_h2 [Tz * Bz * Hz];
__device__ __align__(16) float g_w0r[G4 * Iz];         // tf32-rounded W_ih0
__device__ __align__(16) float g_w1r[G4 * Hz];         // tf32-rounded W_ih1
__device__ __align__(16) float g_h1r[Tz * Bz * Hz];    // tf32-rounded h1

// ---- software grid barrier (128 blocks, all co-resident: 1 block/SM) ----
__device__ unsigned g_bar_count = 0;
__device__ volatile unsigned g_bar_gen = 0;

__device__ __forceinline__ void grid_sync() {
    __syncthreads();
    if (threadIdx.x == 0) {
        __threadfence();
        unsigned gen = g_bar_gen;
        if (atomicAdd(&g_bar_count, 1u) == gridDim.x - 1u) {
            g_bar_count = 0;
            __threadfence();
            g_bar_gen = gen + 1u;
        } else {
            while (g_bar_gen == gen) { }
            __threadfence();
        }
    }
    __syncthreads();
}

// ---------------------------------------------------------------------------
// Transpose x: [B,T,I] -> time-major [T,B,I], tf32-rounded (GEMM-A operand)
// ---------------------------------------------------------------------------
__global__ void transpose_x(const float4* __restrict__ x, float4* __restrict__ xt) {
    int idx = blockIdx.x * blockDim.x + threadIdx.x;   // < 1048576
    int i4 = idx & 63;
    int m  = idx >> 6;
    int t  = m >> 5;
    int b  = m & 31;
    float4 v = x[(b * Tz + t) * (Iz / 4) + i4];
    v.x = t32(v.x); v.y = t32(v.y); v.z = t32(v.z); v.w = t32(v.w);
    xt[idx] = v;
}

// tf32-round a buffer (float4 granularity; n4 = elems/4)
__global__ void round_tf32_k(const float4* __restrict__ in, float4* __restrict__ out, int n4) {
    int i = blockIdx.x * blockDim.x + threadIdx.x;
    if (i < n4) {
        float4 v = in[i];
        v.x = t32(v.x); v.y = t32(v.y); v.z = t32(v.z); v.w = t32(v.w);
        out[i] = v;
    }
}

// ---------------------------------------------------------------------------
// TF32 tensor-core GEMM (TN): C[m][n] = sum_k A[m][k]*W[n][k] + b1[n] + b2[n]
// BM=BN=128, BK=32, 256 thr (8 warps, 2m x 4n grid of 64x32 warp tiles).
// cp.async 2-stage double buffer; smem row stride 36 -> conflict-free LDS.
// A and W MUST be pre-rounded to tf32.
// R12 fix: staging loop covers ALL 128 rows (4 chunks/thread/tile, was 2 -> 
// rows 64..127 were never loaded, garbage accumulation).
// ---------------------------------------------------------------------------
#define GST 36                       // smem row stride (floats)
#define TILE_F (128 * GST)           // floats per (A or B) tile

__global__ __launch_bounds__(256, 2)
void gemm_tf32(const float* __restrict__ A, const float* __restrict__ W,
               const float* __restrict__ b1, const float* __restrict__ b2,
               float* __restrict__ C, int M, int N, int K) {
    extern __shared__ float smg[];   // [2][2][128][GST] : stage, {A,B}

    const int tid = threadIdx.x;
    const int lane = tid & 31;
    const int wid = tid >> 5;
    const int g = lane >> 2, tg = lane & 3;
    const int wm = wid & 1, wn = wid >> 1;        // warp tile: (wm*64, wn*32)
    const int m0 = blockIdx.y * 128, n0 = blockIdx.x * 128;

    unsigned smem_u32;
    asm("{ .reg .u64 t0; cvta.to.shared.u64 t0, %1; cvt.u32.u64 %0, t0; }"
        : "=r"(smem_u32) : "l"(smg));

    // staging: thread -> 4 A-chunks + 4 B-chunks of 16B per stage (full tile)
    const int srow0 = tid >> 3, sc4 = tid & 7;    // rows 0..31 (+32*i), col-chunk 0..7
    const float* Abase = A + (size_t)m0 * K;
    const float* Wbase = W + (size_t)n0 * K;

    float acc[4][4][4];
#pragma unroll
    for (int mt = 0; mt < 4; mt++)
#pragma unroll
        for (int nt = 0; nt < 4; nt++)
#pragma unroll
            for (int i = 0; i < 4; i++) acc[mt][nt][i] = 0.0f;

    const int KT = K >> 5;

    // issue stage s for k-tile kt
    auto issue = [&](int s, int kt) {
        unsigned sA = smem_u32 + (unsigned)(s * 2 * TILE_F) * 4u;
        unsigned sB = sA + (unsigned)TILE_F * 4u;
        const float* Ak = Abase + kt * 32;
        const float* Wk = Wbase + kt * 32;
#pragma unroll
        for (int i = 0; i < 4; i++) {
            int row = srow0 + 32 * i;
            unsigned doff = (unsigned)(row * GST + sc4 * 4) * 4u;
            cp16(sA + doff, Ak + (size_t)row * K + sc4 * 4);
            cp16(sB + doff, Wk + (size_t)row * K + sc4 * 4);
        }
    };

    issue(0, 0);
    asm volatile("cp.async.commit_group;" ::: "memory");
    issue(1, 1);
    asm volatile("cp.async.commit_group;" ::: "memory");

    for (int kt = 0; kt < KT; kt++) {
        asm volatile("cp.async.wait_group 1;" ::: "memory");
        __syncthreads();

        const int s = kt & 1;
        const float* sa = smg + s * 2 * TILE_F + (wm * 64) * GST;
        const float* sb = smg + s * 2 * TILE_F + TILE_F + (wn * 32) * GST;

#pragma unroll
        for (int ks = 0; ks < 4; ks++) {
            const int kk = ks * 8;
            float a[4][4], b[4][2];
#pragma unroll
            for (int mt = 0; mt < 4; mt++) {
                const float* ap = sa + (mt * 16) * GST + kk;
                a[mt][0] = ap[g * GST + tg];
                a[mt][1] = ap[(g + 8) * GST + tg];
                a[mt][2] = ap[g * GST + tg + 4];
                a[mt][3] = ap[(g + 8) * GST + tg + 4];
            }
#pragma unroll
            for (int nt = 0; nt < 4; nt++) {
                const float* bp = sb + (nt * 8) * GST + kk;
                b[nt][0] = bp[g * GST + tg];
                b[nt][1] = bp[g * GST + tg + 4];
            }
#pragma unroll
            for (int mt = 0; mt < 4; mt++)
#pragma unroll
                for (int nt = 0; nt < 4; nt++)
                    mma_tf32(acc[mt][nt], a[mt], b[nt]);
        }
        __syncthreads();
        if (kt + 2 < KT) issue(s, kt + 2);
        asm volatile("cp.async.commit_group;" ::: "memory");
    }

    // epilogue: bias + store (c0,c1 adjacent cols -> float2)
#pragma unroll
    for (int nt = 0; nt < 4; nt++) {
        int col = n0 + wn * 32 + nt * 8 + 2 * tg;
        float bia0 = b1[col]     + (b2 ? b2[col]     : 0.0f);
        float bia1 = b1[col + 1] + (b2 ? b2[col + 1] : 0.0f);
#pragma unroll
        for (int mt = 0; mt < 4; mt++) {
            int row = m0 + wm * 64 + mt * 16 + g;
            float2 v0 = make_float2(acc[mt][nt][0] + bia0, acc[mt][nt][1] + bia1);
            float2 v1 = make_float2(acc[mt][nt][2] + bia0, acc[mt][nt][3] + bia1);
            *(float2*)(C + (size_t)row * N + col) = v0;
            *(float2*)(C + (size_t)(row + 8) * N + col) = v1;
        }
    }
}

// ---------------------------------------------------------------------------
// SGEMM (TN) f32x2 — kept for the FC layer (full precision on the output path)
// ---------------------------------------------------------------------------
template <int MODE>
__global__ __launch_bounds__(256, 2)
void sgemm_tn(const float* __restrict__ A, const float* __restrict__ W,
              const float* __restrict__ b1, const float* __restrict__ b2,
              float* __restrict__ C, int M, int N, int K) {
    __shared__ __align__(16) float As[16][128];
    __shared__ __align__(16) float Bs[16][128];

    const int tid = threadIdx.x;
    const int ty = tid >> 4, tx = tid & 15;
    const int m0 = blockIdx.y * 128, n0 = blockIdx.x * 128;

    ull acc[4][8];
#pragma unroll
    for (int i = 0; i < 4; i++)
#pragma unroll
        for (int j = 0; j < 8; j++) acc[i][j] = 0ULL;

    const float* arow[2];
    int arr[2], acc4[2];
#pragma unroll
    for (int i = 0; i < 2; i++) {
        int item = tid + 256 * i;
        int r = item >> 2, c4 = item & 3;
        arr[i] = r; acc4[i] = c4;
        int m = m0 + r;
        if (MODE == 1) {
            int bb = m / TR, t = m - bb * TR;
            arow[i] = A + (long long)(t * Bz + bb) * K;
        } else {
            arow[i] = A + (long long)m * K;
        }
    }
    const float* wrow[2];
#pragma unroll
    for (int i = 0; i < 2; i++) wrow[i] = W + (long long)(n0 + arr[i]) * K;

    float4 va[2], vb[2];
#pragma unroll
    for (int i = 0; i < 2; i++) {
        va[i] = *(const float4*)(arow[i] + acc4[i] * 4);
        vb[i] = *(const float4*)(wrow[i] + acc4[i] * 4);
    }
#pragma unroll
    for (int i = 0; i < 2; i++) {
        int r = arr[i], c4 = acc4[i];
        As[c4 * 4 + 0][r] = va[i].x; As[c4 * 4 + 1][r] = va[i].y;
        As[c4 * 4 + 2][r] = va[i].z; As[c4 * 4 + 3][r] = va[i].w;
        Bs[c4 * 4 + 0][r] = vb[i].x; Bs[c4 * 4 + 1][r] = vb[i].y;
        Bs[c4 * 4 + 2][r] = vb[i].z; Bs[c4 * 4 + 3][r] = vb[i].w;
    }
    __syncthreads();

    const int KT = K >> 4;
    for (int kt = 0; kt < KT; kt++) {
        if (kt + 1 < KT) {
            int k0n = (kt + 1) << 4;
#pragma unroll
            for (int i = 0; i < 2; i++) {
                va[i] = *(const float4*)(arow[i] + k0n + acc4[i] * 4);
                vb[i] = *(const float4*)(wrow[i] + k0n + acc4[i] * 4);
            }
        }
#pragma unroll
        for (int k = 0; k < 16; k++) {
            ull a2[4];
#pragma unroll
            for (int mp = 0; mp < 4; mp++)
                a2[mp] = *(const ull*)&As[k][ty * 8 + mp * 2];
            float4 bv0 = *(const float4*)&Bs[k][tx * 8];
            float4 bv1 = *(const float4*)&Bs[k][tx * 8 + 4];
            ull bd[8];
            bd[0] = pack2(bv0.x, bv0.x); bd[1] = pack2(bv0.y, bv0.y);
            bd[2] = pack2(bv0.z, bv0.z); bd[3] = pack2(bv0.w, bv0.w);
            bd[4] = pack2(bv1.x, bv1.x); bd[5] = pack2(bv1.y, bv1.y);
            bd[6] = pack2(bv1.z, bv1.z); bd[7] = pack2(bv1.w, bv1.w);
#pragma unroll
            for (int mp = 0; mp < 4; mp++)
#pragma unroll
                for (int n = 0; n < 8; n++) fma2(acc[mp][n], a2[mp], bd[n]);
        }
        if (kt + 1 < KT) {
            __syncthreads();
#pragma unroll
            for (int i = 0; i < 2; i++) {
                int r = arr[i], c4 = acc4[i];
                As[c4 * 4 + 0][r] = va[i].x; As[c4 * 4 + 1][r] = va[i].y;
                As[c4 * 4 + 2][r] = va[i].z; As[c4 * 4 + 3][r] = va[i].w;
                Bs[c4 * 4 + 0][r] = vb[i].x; Bs[c4 * 4 + 1][r] = vb[i].y;
                Bs[c4 * 4 + 2][r] = vb[i].z; Bs[c4 * 4 + 3][r] = vb[i].w;
            }
            __syncthreads();
        }
    }

    float bb[8];
#pragma unroll
    for (int n = 0; n < 8; n++) {
        int col = n0 + tx * 8 + n;
        bb[n] = b1[col] + (b2 ? b2[col] : 0.0f);
    }
#pragma unroll
    for (int mp = 0; mp < 4; mp++) {
        float lo[8], hi[8];
#pragma unroll
        for (int n = 0; n < 8; n++) unpack2(acc[mp][n], lo[n], hi[n]);
        int row0 = m0 + ty * 8 + mp * 2;
        float* c0 = C + (long long)row0 * N + n0 + tx * 8;
        float* c1 = c0 + N;
        float o0[8], o1[8];
#pragma unroll
        for (int n = 0; n < 8; n++) { o0[n] = lo[n] + bb[n]; o1[n] = hi[n] + bb[n]; }
        *(float4*)(c0)     = make_float4(o0[0], o0[1], o0[2], o0[3]);
        *(float4*)(c0 + 4) = make_float4(o0[4], o0[5], o0[6], o0[7]);
        *(float4*)(c1)     = make_float4(o1[0], o1[1], o1[2], o1[3]);
        *(float4*)(c1 + 4) = make_float4(o1[4], o1[5], o1[6], o1[7]);
    }
}

// ---------------------------------------------------------------------------
// Persistent LSTM recurrence — R9 version (proven fastest): ring reduction +
// cp.async staging. 128 blocks x 256 threads.
// ---------------------------------------------------------------------------
__global__ __launch_bounds__(256, 1)
void lstm_recurrence(const float* __restrict__ xg,   // [T][B][4H]
                     const float* __restrict__ Whh,  // [4H][H]
                     float* __restrict__ hout) {     // [T][B][H]
    extern __shared__ float sh[];                    // [32][1024] = 128KB
    const int tid = threadIdx.x;
    const int lane = tid & 31;
    const int u = tid >> 5;
    const int j = blockIdx.x * 8 + u;
    const int srcl = (lane + 1) & 31;

    unsigned sh_u32;
    asm("{ .reg .u64 t0; cvta.to.shared.u64 t0, %1; cvt.u32.u64 %0, t0; }"
        : "=r"(sh_u32) : "l"(sh));

    ull wi[16], wf[16], wg[16], wo[16];
    {
        const ulonglong2* Wi = (const ulonglong2*)(Whh + (size_t)j * Hz) + lane;
        const ulonglong2* Wf = (const ulonglong2*)(Whh + (size_t)(Hz + j) * Hz) + lane;
        const ulonglong2* Wg = (const ulonglong2*)(Whh + (size_t)(2 * Hz + j) * Hz) + lane;
        const ulonglong2* Wo = (const ulonglong2*)(Whh + (size_t)(3 * Hz + j) * Hz) + lane;
#pragma unroll
        for (int m = 0; m < 8; m++) {
            ulonglong2 a = Wi[32 * m]; wi[2 * m] = a.x; wi[2 * m + 1] = a.y;
            ulonglong2 b = Wf[32 * m]; wf[2 * m] = b.x; wf[2 * m + 1] = b.y;
            ulonglong2 c = Wg[32 * m]; wg[2 * m] = c.x; wg[2 * m + 1] = c.y;
            ulonglong2 d = Wo[32 * m]; wo[2 * m] = d.x; wo[2 * m + 1] = d.y;
        }
    }

    float creg = 0.0f;

    for (int t = 0; t < Tz; t++) {
        const float* xr = xg + (size_t)t * Bz * G4 + (size_t)lane * G4;
        float xi = __ldg(xr + j);
        float xf = __ldg(xr + Hz + j);
        float xgv = __ldg(xr + 2 * Hz + j);
        float xo = __ldg(xr + 3 * Hz + j);

        if (t > 0) {
            const float* hp = hout + (size_t)(t - 1) * Bz * Hz;
#pragma unroll
            for (int i = 0; i < 32; i++) {
                int idx = tid + 256 * i;
                cp16(sh_u32 + (unsigned)idx * 16u, hp + (size_t)idx * 4);
            }
            asm volatile("cp.async.commit_group;" ::: "memory");
            asm volatile("cp.async.wait_group 0;" ::: "memory");
        }
        __syncthreads();

        ull r01 = 0ULL, r23 = 0ULL;
        if (t > 0) {
#pragma unroll 2
            for (int s = 0; s < 32; s++) {
                const int b = (lane + s) & 31;
                const ulonglong2* hb = (const ulonglong2*)(sh + b * Hz) + lane;
                ull ai = 0, af = 0, ag = 0, ao = 0;
#pragma unroll
                for (int m = 0; m < 8; m++) {
                    ulonglong2 h2 = hb[32 * m];
                    fma2(ai, h2.x, wi[2 * m]);     fma2(af, h2.x, wf[2 * m]);
                    fma2(ag, h2.x, wg[2 * m]);     fma2(ao, h2.x, wo[2 * m]);
                    fma2(ai, h2.y, wi[2 * m + 1]); fma2(af, h2.y, wf[2 * m + 1]);
                    fma2(ag, h2.y, wg[2 * m + 1]); fma2(ao, h2.y, wo[2 * m + 1]);
                }
                float l0, h0;
                unpack2(ai, l0, h0); float iv = l0 + h0;
                unpack2(af, l0, h0); float fv = l0 + h0;
                unpack2(ag, l0, h0); float gv = l0 + h0;
                unpack2(ao, l0, h0); float ov = l0 + h0;
                r01 = add2(r01, pack2(iv, fv));
                r23 = add2(r23, pack2(gv, ov));
                r01 = __shfl_sync(0xffffffffu, r01, srcl);
                r23 = __shfl_sync(0xffffffffu, r23, srcl);
            }
        }

        float pi, pf, pg, po;
        unpack2(r01, pi, pf);
        unpack2(r23, pg, po);
        pi += xi; pf += xf; pg += xgv; po += xo;

        float si = sig_f(pi);
        float sf = sig_f(pf);
        float so = sig_f(po);
        creg = sf * creg + si * tanh_f(pg);
        float hn = so * tanh_f(creg);
        hout[(size_t)t * Bz * Hz + (size_t)lane * Hz + j] = hn;

        grid_sync();
    }
}

// ---------------------------------------------------------------------------
extern "C" void kernel_launch(void* const* d_in, const int* in_sizes, int n_in,
                              void* d_out, int out_size) {
    (void)in_sizes; (void)n_in; (void)out_size;
    const float* x     = (const float*)d_in[0];
    const float* W_ih0 = (const float*)d_in[1];
    const float* W_hh0 = (const float*)d_in[2];
    const float* b_ih0 = (const float*)d_in[3];
    const float* b_hh0 = (const float*)d_in[4];
    const float* W_ih1 = (const float*)d_in[5];
    const float* W_hh1 = (const float*)d_in[6];
    const float* b_ih1 = (const float*)d_in[7];
    const float* b_hh1 = (const float*)d_in[8];
    const float* W_fc  = (const float*)d_in[9];
    const float* b_fc  = (const float*)d_in[10];
    float* out = (float*)d_out;

    float *xt, *xgp, *h1, *h2, *w0r, *w1r, *h1r;
    cudaGetSymbolAddress((void**)&xt,  g_xt);
    cudaGetSymbolAddress((void**)&xgp, g_xg);
    cudaGetSymbolAddress((void**)&h1,  g_h1);
    cudaGetSymbolAddress((void**)&h2,  g_h2);
    cudaGetSymbolAddress((void**)&w0r, g_w0r);
    cudaGetSymbolAddress((void**)&w1r, g_w1r);
    cudaGetSymbolAddress((void**)&h1r, g_h1r);

    const int REC_SMEM = Bz * Hz * (int)sizeof(float);           // 128KB
    const int GEMM_SMEM = 2 * 2 * TILE_F * (int)sizeof(float);   // 73728B
    cudaFuncSetAttribute(lstm_recurrence,
                         cudaFuncAttributeMaxDynamicSharedMemorySize, REC_SMEM);
    cudaFuncSetAttribute(gemm_tf32,
                         cudaFuncAttributeMaxDynamicSharedMemorySize, GEMM_SMEM);

    // x -> time-major (tf32-rounded); round weights
    transpose_x<<<4096, 256>>>((const float4*)x, (float4*)xt);
    round_tf32_k<<<(G4 * Iz / 4 + 255) / 256, 256>>>((const float4*)W_ih0, (float4*)w0r, G4 * Iz / 4);
    round_tf32_k<<<(G4 * Hz / 4 + 255) / 256, 256>>>((const float4*)W_ih1, (float4*)w1r, G4 * Hz / 4);

    // layer 0: tf32 input GEMM [16384,256]x[256,4096]^T + recurrence
    gemm_tf32<<<dim3(G4 / 128, (Tz * Bz) / 128), 256, GEMM_SMEM>>>(
        xt, w0r, b_ih0, b_hh0, xgp, Tz * Bz, G4, Iz);
    lstm_recurrence<<<128, 256, REC_SMEM>>>(xgp, W_hh0, h1);

    // round h1, layer 1: tf32 input GEMM [16384,1024]x[1024,4096]^T + recurrence
    round_tf32_k<<<(Tz * Bz * Hz / 4 + 255) / 256, 256>>>((const float4*)h1, (float4*)h1r, Tz * Bz * Hz / 4);
    gemm_tf32<<<dim3(G4 / 128, (Tz * Bz) / 128), 256, GEMM_SMEM>>>(
        h1r, w1r, b_ih1, b_hh1, xgp, Tz * Bz, G4, Hz);
    lstm_recurrence<<<128, 256, REC_SMEM>>>(xgp, W_hh1, h2);

    // FC over truncated sequence (full fp32): out[b,t,o], m = b*500 + t
    sgemm_tn<1><<<dim3(Oz / 128, (Bz * TR) / 128), 256>>>(h2, W_fc, b_fc, nullptr,
                                                          out, Bz * TR, Oz, Hz);
}

// round 14
// speedup vs baseline: 1.6301x; 1.2586x over previous
#include <cuda_runtime.h>
#include <math.h>

#define Bz 32
#define Tz 512
#define Iz 256
#define Hz 1024
#define G4 4096
#define Oz 512
#define TR 500

typedef unsigned long long ull;

// ---- packed f32x2 helpers (sm_103a) ----
__device__ __forceinline__ ull pack2(float x, float y) {
    ull r; asm("mov.b64 %0, {%1,%2};" : "=l"(r) : "f"(x), "f"(y)); return r;
}
__device__ __forceinline__ void unpack2(ull v, float& x, float& y) {
    asm("mov.b64 {%0,%1}, %2;" : "=f"(x), "=f"(y) : "l"(v));
}
__device__ __forceinline__ void fma2(ull& d, ull a, ull b) {
    asm("fma.rn.f32x2 %0, %1, %2, %0;" : "+l"(d) : "l"(a), "l"(b));
}

__device__ __forceinline__ float sig_f(float x) {
    return __fdividef(1.0f, 1.0f + __expf(-x));
}
__device__ __forceinline__ float tanh_f(float x) {
    return 1.0f - __fdividef(2.0f, __expf(2.0f * x) + 1.0f);
}

// round-to-nearest tf32
__device__ __forceinline__ float t32(float x) {
    unsigned u; asm("cvt.rna.tf32.f32 %0, %1;" : "=r"(u) : "f"(x));
    return __uint_as_float(u);
}

// cp.async 16B: global -> shared
__device__ __forceinline__ void cp16(unsigned smem_addr, const void* gptr) {
    asm volatile("cp.async.cg.shared.global [%0], [%1], 16;"
                 :: "r"(smem_addr), "l"(gptr) : "memory");
}

// mma.sync m16n8k8 tf32: D += A*B (accumulate in-place)
__device__ __forceinline__ void mma_tf32(float* c, const float* a, const float* b) {
    asm volatile(
        "mma.sync.aligned.m16n8k8.row.col.f32.tf32.tf32.f32 "
        "{%0,%1,%2,%3}, {%4,%5,%6,%7}, {%8,%9}, {%0,%1,%2,%3};"
        : "+f"(c[0]), "+f"(c[1]), "+f"(c[2]), "+f"(c[3])
        : "r"(__float_as_uint(a[0])), "r"(__float_as_uint(a[1])),
          "r"(__float_as_uint(a[2])), "r"(__float_as_uint(a[3])),
          "r"(__float_as_uint(b[0])), "r"(__float_as_uint(b[1])));
}

// ---- scratch (device globals: allocation-free) ----
__device__ __align__(16) float g_xt [Tz * Bz * Iz];    // tf32-rounded x, time-major
__device__ __align__(16) float g_xg [Tz * Bz * G4];
__device__ __align__(16) float g_h1r[Tz * Bz * Hz];    // layer0 h, tf32-rounded
__device__ __align__(16) float g_h2r[Tz * Bz * Hz];    // layer1 h, tf32-rounded
__device__ __align__(16) float g_h2 [Tz * Bz * Hz];    // layer1 h, full fp32 (FC)
__device__ __align__(16) float g_w0r[G4 * Iz];         // tf32-rounded W_ih0
__device__ __align__(16) float g_w1r[G4 * Hz];         // tf32-rounded W_ih1

// ---- software grid barrier (128 blocks, all co-resident: 1 block/SM) ----
__device__ unsigned g_bar_count = 0;
__device__ volatile unsigned g_bar_gen = 0;

__device__ __forceinline__ void grid_sync() {
    __syncthreads();
    if (threadIdx.x == 0) {
        __threadfence();
        unsigned gen = g_bar_gen;
        if (atomicAdd(&g_bar_count, 1u) == gridDim.x - 1u) {
            g_bar_count = 0;
            __threadfence();
            g_bar_gen = gen + 1u;
        } else {
            while (g_bar_gen == gen) { }
            __threadfence();
        }
    }
    __syncthreads();
}

// ---------------------------------------------------------------------------
// Transpose x: [B,T,I] -> time-major [T,B,I], tf32-rounded
// ---------------------------------------------------------------------------
__global__ void transpose_x(const float4* __restrict__ x, float4* __restrict__ xt) {
    int idx = blockIdx.x * blockDim.x + threadIdx.x;   // < 1048576
    int i4 = idx & 63;
    int m  = idx >> 6;
    int t  = m >> 5;
    int b  = m & 31;
    float4 v = x[(b * Tz + t) * (Iz / 4) + i4];
    v.x = t32(v.x); v.y = t32(v.y); v.z = t32(v.z); v.w = t32(v.w);
    xt[idx] = v;
}

__global__ void round_tf32_k(const float4* __restrict__ in, float4* __restrict__ out, int n4) {
    int i = blockIdx.x * blockDim.x + threadIdx.x;
    if (i < n4) {
        float4 v = in[i];
        v.x = t32(v.x); v.y = t32(v.y); v.z = t32(v.z); v.w = t32(v.w);
        out[i] = v;
    }
}

// ---------------------------------------------------------------------------
// TF32 tensor-core GEMM (TN) — R12 (passing). BM=BN=128, BK=32, 8 warps.
// ---------------------------------------------------------------------------
#define GST 36
#define TILE_F (128 * GST)

__global__ __launch_bounds__(256, 2)
void gemm_tf32(const float* __restrict__ A, const float* __restrict__ W,
               const float* __restrict__ b1, const float* __restrict__ b2,
               float* __restrict__ C, int M, int N, int K) {
    extern __shared__ float smg[];

    const int tid = threadIdx.x;
    const int lane = tid & 31;
    const int wid = tid >> 5;
    const int g = lane >> 2, tg = lane & 3;
    const int wm = wid & 1, wn = wid >> 1;
    const int m0 = blockIdx.y * 128, n0 = blockIdx.x * 128;

    unsigned smem_u32;
    asm("{ .reg .u64 t0; cvta.to.shared.u64 t0, %1; cvt.u32.u64 %0, t0; }"
        : "=r"(smem_u32) : "l"(smg));

    const int srow0 = tid >> 3, sc4 = tid & 7;
    const float* Abase = A + (size_t)m0 * K;
    const float* Wbase = W + (size_t)n0 * K;

    float acc[4][4][4];
#pragma unroll
    for (int mt = 0; mt < 4; mt++)
#pragma unroll
        for (int nt = 0; nt < 4; nt++)
#pragma unroll
            for (int i = 0; i < 4; i++) acc[mt][nt][i] = 0.0f;

    const int KT = K >> 5;

    auto issue = [&](int s, int kt) {
        unsigned sA = smem_u32 + (unsigned)(s * 2 * TILE_F) * 4u;
        unsigned sB = sA + (unsigned)TILE_F * 4u;
        const float* Ak = Abase + kt * 32;
        const float* Wk = Wbase + kt * 32;
#pragma unroll
        for (int i = 0; i < 4; i++) {
            int row = srow0 + 32 * i;
            unsigned doff = (unsigned)(row * GST + sc4 * 4) * 4u;
            cp16(sA + doff, Ak + (size_t)row * K + sc4 * 4);
            cp16(sB + doff, Wk + (size_t)row * K + sc4 * 4);
        }
    };

    issue(0, 0);
    asm volatile("cp.async.commit_group;" ::: "memory");
    issue(1, 1);
    asm volatile("cp.async.commit_group;" ::: "memory");

    for (int kt = 0; kt < KT; kt++) {
        asm volatile("cp.async.wait_group 1;" ::: "memory");
        __syncthreads();

        const int s = kt & 1;
        const float* sa = smg + s * 2 * TILE_F + (wm * 64) * GST;
        const float* sb = smg + s * 2 * TILE_F + TILE_F + (wn * 32) * GST;

#pragma unroll
        for (int ks = 0; ks < 4; ks++) {
            const int kk = ks * 8;
            float a[4][4], b[4][2];
#pragma unroll
            for (int mt = 0; mt < 4; mt++) {
                const float* ap = sa + (mt * 16) * GST + kk;
                a[mt][0] = ap[g * GST + tg];
                a[mt][1] = ap[(g + 8) * GST + tg];
                a[mt][2] = ap[g * GST + tg + 4];
                a[mt][3] = ap[(g + 8) * GST + tg + 4];
            }
#pragma unroll
            for (int nt = 0; nt < 4; nt++) {
                const float* bp = sb + (nt * 8) * GST + kk;
                b[nt][0] = bp[g * GST + tg];
                b[nt][1] = bp[g * GST + tg + 4];
            }
#pragma unroll
            for (int mt = 0; mt < 4; mt++)
#pragma unroll
                for (int nt = 0; nt < 4; nt++)
                    mma_tf32(acc[mt][nt], a[mt], b[nt]);
        }
        __syncthreads();
        if (kt + 2 < KT) issue(s, kt + 2);
        asm volatile("cp.async.commit_group;" ::: "memory");
    }

#pragma unroll
    for (int nt = 0; nt < 4; nt++) {
        int col = n0 + wn * 32 + nt * 8 + 2 * tg;
        float bia0 = b1[col]     + (b2 ? b2[col]     : 0.0f);
        float bia1 = b1[col + 1] + (b2 ? b2[col + 1] : 0.0f);
#pragma unroll
        for (int mt = 0; mt < 4; mt++) {
            int row = m0 + wm * 64 + mt * 16 + g;
            float2 v0 = make_float2(acc[mt][nt][0] + bia0, acc[mt][nt][1] + bia1);
            float2 v1 = make_float2(acc[mt][nt][2] + bia0, acc[mt][nt][3] + bia1);
            *(float2*)(C + (size_t)row * N + col) = v0;
            *(float2*)(C + (size_t)(row + 8) * N + col) = v1;
        }
    }
}

// ---------------------------------------------------------------------------
// SGEMM (TN) f32x2 — FC layer (full precision on the output path)
// ---------------------------------------------------------------------------
__global__ __launch_bounds__(256, 2)
void sgemm_fc(const float* __restrict__ A, const float* __restrict__ W,
              const float* __restrict__ b1,
              float* __restrict__ C, int M, int N, int K) {
    __shared__ __align__(16) float As[16][128];
    __shared__ __align__(16) float Bs[16][128];

    const int tid = threadIdx.x;
    const int ty = tid >> 4, tx = tid & 15;
    const int m0 = blockIdx.y * 128, n0 = blockIdx.x * 128;

    ull acc[4][8];
#pragma unroll
    for (int i = 0; i < 4; i++)
#pragma unroll
        for (int j = 0; j < 8; j++) acc[i][j] = 0ULL;

    const float* arow[2];
    int arr[2], acc4[2];
#pragma unroll
    for (int i = 0; i < 2; i++) {
        int item = tid + 256 * i;
        int r = item >> 2, c4 = item & 3;
        arr[i] = r; acc4[i] = c4;
        int m = m0 + r;
        int bb = m / TR, t = m - bb * TR;
        arow[i] = A + (long long)(t * Bz + bb) * K;
    }
    const float* wrow[2];
#pragma unroll
    for (int i = 0; i < 2; i++) wrow[i] = W + (long long)(n0 + arr[i]) * K;

    float4 va[2], vb[2];
#pragma unroll
    for (int i = 0; i < 2; i++) {
        va[i] = *(const float4*)(arow[i] + acc4[i] * 4);
        vb[i] = *(const float4*)(wrow[i] + acc4[i] * 4);
    }
#pragma unroll
    for (int i = 0; i < 2; i++) {
        int r = arr[i], c4 = acc4[i];
        As[c4 * 4 + 0][r] = va[i].x; As[c4 * 4 + 1][r] = va[i].y;
        As[c4 * 4 + 2][r] = va[i].z; As[c4 * 4 + 3][r] = va[i].w;
        Bs[c4 * 4 + 0][r] = vb[i].x; Bs[c4 * 4 + 1][r] = vb[i].y;
        Bs[c4 * 4 + 2][r] = vb[i].z; Bs[c4 * 4 + 3][r] = vb[i].w;
    }
    __syncthreads();

    const int KT = K >> 4;
    for (int kt = 0; kt < KT; kt++) {
        if (kt + 1 < KT) {
            int k0n = (kt + 1) << 4;
#pragma unroll
            for (int i = 0; i < 2; i++) {
                va[i] = *(const float4*)(arow[i] + k0n + acc4[i] * 4);
                vb[i] = *(const float4*)(wrow[i] + k0n + acc4[i] * 4);
            }
        }
#pragma unroll
        for (int k = 0; k < 16; k++) {
            ull a2[4];
#pragma unroll
            for (int mp = 0; mp < 4; mp++)
                a2[mp] = *(const ull*)&As[k][ty * 8 + mp * 2];
            float4 bv0 = *(const float4*)&Bs[k][tx * 8];
            float4 bv1 = *(const float4*)&Bs[k][tx * 8 + 4];
            ull bd[8];
            bd[0] = pack2(bv0.x, bv0.x); bd[1] = pack2(bv0.y, bv0.y);
            bd[2] = pack2(bv0.z, bv0.z); bd[3] = pack2(bv0.w, bv0.w);
            bd[4] = pack2(bv1.x, bv1.x); bd[5] = pack2(bv1.y, bv1.y);
            bd[6] = pack2(bv1.z, bv1.z); bd[7] = pack2(bv1.w, bv1.w);
#pragma unroll
            for (int mp = 0; mp < 4; mp++)
#pragma unroll
                for (int n = 0; n < 8; n++) fma2(acc[mp][n], a2[mp], bd[n]);
        }
        if (kt + 1 < KT) {
            __syncthreads();
#pragma unroll
            for (int i = 0; i < 2; i++) {
                int r = arr[i], c4 = acc4[i];
                As[c4 * 4 + 0][r] = va[i].x; As[c4 * 4 + 1][r] = va[i].y;
                As[c4 * 4 + 2][r] = va[i].z; As[c4 * 4 + 3][r] = va[i].w;
                Bs[c4 * 4 + 0][r] = vb[i].x; Bs[c4 * 4 + 1][r] = vb[i].y;
                Bs[c4 * 4 + 2][r] = vb[i].z; Bs[c4 * 4 + 3][r] = vb[i].w;
            }
            __syncthreads();
        }
    }

    float bb[8];
#pragma unroll
    for (int n = 0; n < 8; n++) bb[n] = b1[n0 + tx * 8 + n];
#pragma unroll
    for (int mp = 0; mp < 4; mp++) {
        float lo[8], hi[8];
#pragma unroll
        for (int n = 0; n < 8; n++) unpack2(acc[mp][n], lo[n], hi[n]);
        int row0 = m0 + ty * 8 + mp * 2;
        float* c0 = C + (long long)row0 * N + n0 + tx * 8;
        float* c1 = c0 + N;
        float o0[8], o1[8];
#pragma unroll
        for (int n = 0; n < 8; n++) { o0[n] = lo[n] + bb[n]; o1[n] = hi[n] + bb[n]; }
        *(float4*)(c0)     = make_float4(o0[0], o0[1], o0[2], o0[3]);
        *(float4*)(c0 + 4) = make_float4(o0[4], o0[5], o0[6], o0[7]);
        *(float4*)(c1)     = make_float4(o1[0], o1[1], o1[2], o1[3]);
        *(float4*)(c1 + 4) = make_float4(o1[4], o1[5], o1[6], o1[7]);
    }
}

// ---------------------------------------------------------------------------
// R13: tensor-core persistent LSTM recurrence.
// 128 blocks x 256 threads (8 warps). Block owns 32 gate-rows n = gate*8+unit
// (units j0..j0+7). W slice (32x1024 tf32) persistent in smem (stride 1028,
// conflict-free). Per step: h[t-1] (tf32-rounded buffer hr) staged in 4x
// (32x256) cp.async double-buffered chunks (stride 260). Warps = (wm:2 m16) x
// (wn:2 n16) x (wk:2 k8-parity). Per warp/step: 64 k8-tiles x (4 A-LDS +
// 4 B-LDS + 2 HMMA). wk-partials + gate gather via 8.7KB smem epilogue.
// Writes hr[t] (tf32) and optionally hf[t] (full fp32, for FC).
// ---------------------------------------------------------------------------
#define WST 1028     // W smem row stride (1028%32==4 -> (4g+tg) conflict-free)
#define HST 260      // h smem row stride (260%32==4)
#define CK  256      // h k-chunk

__global__ __launch_bounds__(256, 1)
void lstm_rec_tc(const float* __restrict__ xg,    // [T][B][4H]
                 const float* __restrict__ Whh,   // [4H][H] fp32
                 float* __restrict__ hr,          // [T][B][H] tf32-rounded out
                 float* __restrict__ hf) {        // [T][B][H] fp32 out (nullable)
    extern __shared__ float sm[];
    float* Wsm = sm;                         // [32][WST]
    float* hsm = sm + 32 * WST;              // [2][32][HST]
    float* gsm = hsm + 2 * 32 * HST;         // [2][32][34]

    const int tid = threadIdx.x;
    const int lane = tid & 31, wid = tid >> 5;
    const int wm = wid & 1, wn = (wid >> 1) & 1, wk = wid >> 2;
    const int g = lane >> 2, tg = lane & 3;
    const int j0 = blockIdx.x * 8;
    const int eu = tid & 7, eb = tid >> 3;   // epilogue role: (batch eb, unit eu)
    const int j = j0 + eu;

    unsigned hsm_u32;
    asm("{ .reg .u64 t0; cvta.to.shared.u64 t0, %1; cvt.u32.u64 %0, t0; }"
        : "=r"(hsm_u32) : "l"(hsm));

    // ---- preload W slice (tf32-rounded): n = gate*8+unit -> W row gate*H + j0+unit
    {
        int n = tid >> 3, kl = tid & 7;
        int gate = n >> 3, unit = n & 7;
        const float4* src = (const float4*)(Whh + (size_t)(gate * Hz + j0 + unit) * Hz);
        float* dst = Wsm + n * WST;
#pragma unroll 8
        for (int kk = 0; kk < 32; kk++) {
            int k4 = kl + kk * 8;
            float4 v = src[k4];
            v.x = t32(v.x); v.y = t32(v.y); v.z = t32(v.z); v.w = t32(v.w);
            *(float4*)(dst + k4 * 4) = v;
        }
    }
    __syncthreads();

    // per-chunk stage: 2048 cp16, 8/thread, coalesced
    auto stage = [&](int c, const float* hp) {
#pragma unroll
        for (int i = 0; i < 8; i++) {
            int idx = i * 256 + tid;
            int row = idx >> 6, ch = idx & 63;
            cp16(hsm_u32 + (unsigned)(((c & 1) * 32 + row) * HST + ch * 4) * 4u,
                 hp + (size_t)row * Hz + c * CK + ch * 4);
        }
        asm volatile("cp.async.commit_group;" ::: "memory");
    };

    float creg = 0.0f;   // c[eb][j] register-resident

    for (int t = 0; t < Tz; t++) {
        const float* xr = xg + (size_t)t * Bz * G4 + (size_t)eb * G4;
        float pi = __ldg(xr + j);
        float pf = __ldg(xr + Hz + j);
        float pg = __ldg(xr + 2 * Hz + j);
        float po = __ldg(xr + 3 * Hz + j);

        if (t > 0) {
            const float* hp = hr + (size_t)(t - 1) * Bz * Hz;
            stage(0, hp);
            stage(1, hp);

            float c0[4] = {0, 0, 0, 0}, c1[4] = {0, 0, 0, 0};
            for (int c = 0; c < 4; c++) {
                if (c < 3) asm volatile("cp.async.wait_group 1;" ::: "memory");
                else       asm volatile("cp.async.wait_group 0;" ::: "memory");
                __syncthreads();

                const float* hb = hsm + (c & 1) * 32 * HST + (wm * 16) * HST;
                const float* w0 = Wsm + ((2 * wn) * 8 + g) * WST;
                const float* w1 = Wsm + ((2 * wn + 1) * 8 + g) * WST;
#pragma unroll 4
                for (int i = 0; i < 16; i++) {
                    int ko = (2 * i + wk) * 8;
                    float a[4];
                    a[0] = hb[g * HST + ko + tg];
                    a[1] = hb[(g + 8) * HST + ko + tg];
                    a[2] = hb[g * HST + ko + tg + 4];
                    a[3] = hb[(g + 8) * HST + ko + tg + 4];
                    int kg = c * CK + ko;
                    float b0[2], b1[2];
                    b0[0] = w0[kg + tg]; b0[1] = w0[kg + tg + 4];
                    b1[0] = w1[kg + tg]; b1[1] = w1[kg + tg + 4];
                    mma_tf32(c0, a, b0);
                    mma_tf32(c1, a, b1);
                }
                __syncthreads();
                if (c < 2) stage(c + 2, hp);
            }

            // publish wk-partials: gsm[wk][m][n], stride 34 (float2-aligned)
            float* gp = gsm + wk * (32 * 34);
            int nn0 = (2 * wn) * 8 + 2 * tg, nn1 = (2 * wn + 1) * 8 + 2 * tg;
            int mr0 = wm * 16 + g, mr1 = wm * 16 + 8 + g;
            *(float2*)(gp + mr0 * 34 + nn0) = make_float2(c0[0], c0[1]);
            *(float2*)(gp + mr1 * 34 + nn0) = make_float2(c0[2], c0[3]);
            *(float2*)(gp + mr0 * 34 + nn1) = make_float2(c1[0], c1[1]);
            *(float2*)(gp + mr1 * 34 + nn1) = make_float2(c1[2], c1[3]);
            __syncthreads();

            // gather gates for (eb, eu): n = gate*8+eu, sum both wk parts
            const float* g0 = gsm + eb * 34;
            const float* g1 = gsm + 32 * 34 + eb * 34;
            pi += g0[eu]      + g1[eu];
            pf += g0[8 + eu]  + g1[8 + eu];
            pg += g0[16 + eu] + g1[16 + eu];
            po += g0[24 + eu] + g1[24 + eu];
        }

        float si = sig_f(pi);
        float sf = sig_f(pf);
        float so = sig_f(po);
        creg = sf * creg + si * tanh_f(pg);
        float hn = so * tanh_f(creg);
        size_t oidx = (size_t)t * Bz * Hz + (size_t)eb * Hz + j;
        if (hf) hf[oidx] = hn;
        hr[oidx] = t32(hn);

        grid_sync();
    }
}

// ---------------------------------------------------------------------------
extern "C" void kernel_launch(void* const* d_in, const int* in_sizes, int n_in,
                              void* d_out, int out_size) {
    (void)in_sizes; (void)n_in; (void)out_size;
    const float* x     = (const float*)d_in[0];
    const float* W_ih0 = (const float*)d_in[1];
    const float* W_hh0 = (const float*)d_in[2];
    const float* b_ih0 = (const float*)d_in[3];
    const float* b_hh0 = (const float*)d_in[4];
    const float* W_ih1 = (const float*)d_in[5];
    const float* W_hh1 = (const float*)d_in[6];
    const float* b_ih1 = (const float*)d_in[7];
    const float* b_hh1 = (const float*)d_in[8];
    const float* W_fc  = (const float*)d_in[9];
    const float* b_fc  = (const float*)d_in[10];
    float* out = (float*)d_out;

    float *xt, *xgp, *h1r, *h2r, *h2, *w0r, *w1r;
    cudaGetSymbolAddress((void**)&xt,  g_xt);
    cudaGetSymbolAddress((void**)&xgp, g_xg);
    cudaGetSymbolAddress((void**)&h1r, g_h1r);
    cudaGetSymbolAddress((void**)&h2r, g_h2r);
    cudaGetSymbolAddress((void**)&h2,  g_h2);
    cudaGetSymbolAddress((void**)&w0r, g_w0r);
    cudaGetSymbolAddress((void**)&w1r, g_w1r);

    const int REC_SMEM  = (32 * WST + 2 * 32 * HST + 2 * 32 * 34) * (int)sizeof(float); // 206848B
    const int GEMM_SMEM = 2 * 2 * TILE_F * (int)sizeof(float);                          // 73728B
    cudaFuncSetAttribute(lstm_rec_tc,
                         cudaFuncAttributeMaxDynamicSharedMemorySize, REC_SMEM);
    cudaFuncSetAttribute(gemm_tf32,
                         cudaFuncAttributeMaxDynamicSharedMemorySize, GEMM_SMEM);

    // x -> time-major (tf32); round input-GEMM weights
    transpose_x<<<4096, 256>>>((const float4*)x, (float4*)xt);
    round_tf32_k<<<(G4 * Iz / 4 + 255) / 256, 256>>>((const float4*)W_ih0, (float4*)w0r, G4 * Iz / 4);
    round_tf32_k<<<(G4 * Hz / 4 + 255) / 256, 256>>>((const float4*)W_ih1, (float4*)w1r, G4 * Hz / 4);

    // layer 0: tf32 input GEMM + tensor-core recurrence (writes h1r tf32)
    gemm_tf32<<<dim3(G4 / 128, (Tz * Bz) / 128), 256, GEMM_SMEM>>>(
        xt, w0r, b_ih0, b_hh0, xgp, Tz * Bz, G4, Iz);
    lstm_rec_tc<<<128, 256, REC_SMEM>>>(xgp, W_hh0, h1r, nullptr);

    // layer 1: tf32 input GEMM (A = h1r, already rounded) + recurrence
    gemm_tf32<<<dim3(G4 / 128, (Tz * Bz) / 128), 256, GEMM_SMEM>>>(
        h1r, w1r, b_ih1, b_hh1, xgp, Tz * Bz, G4, Hz);
    lstm_rec_tc<<<128, 256, REC_SMEM>>>(xgp, W_hh1, h2r, h2);

    // FC over truncated sequence (full fp32): out[b,t,o], m = b*500 + t
    sgemm_fc<<<dim3(Oz / 128, (Bz * TR) / 128), 256>>>(h2, W_fc, b_fc,
                                                       out, Bz * TR, Oz, Hz);
}

// round 15
// speedup vs baseline: 1.8485x; 1.1340x over previous
#include <cuda_runtime.h>
#include <math.h>

#define Bz 32
#define Tz 512
#define Iz 256
#define Hz 1024
#define G4 4096
#define Oz 512
#define TR 500

typedef unsigned long long ull;

// ---- packed f32x2 helpers (sm_103a) ----
__device__ __forceinline__ ull pack2(float x, float y) {
    ull r; asm("mov.b64 %0, {%1,%2};" : "=l"(r) : "f"(x), "f"(y)); return r;
}
__device__ __forceinline__ void unpack2(ull v, float& x, float& y) {
    asm("mov.b64 {%0,%1}, %2;" : "=f"(x), "=f"(y) : "l"(v));
}
__device__ __forceinline__ void fma2(ull& d, ull a, ull b) {
    asm("fma.rn.f32x2 %0, %1, %2, %0;" : "+l"(d) : "l"(a), "l"(b));
}

__device__ __forceinline__ float sig_f(float x) {
    return __fdividef(1.0f, 1.0f + __expf(-x));
}
__device__ __forceinline__ float tanh_f(float x) {
    return 1.0f - __fdividef(2.0f, __expf(2.0f * x) + 1.0f);
}

// round-to-nearest tf32
__device__ __forceinline__ float t32(float x) {
    unsigned u; asm("cvt.rna.tf32.f32 %0, %1;" : "=r"(u) : "f"(x));
    return __uint_as_float(u);
}

// cp.async 16B: global -> shared
__device__ __forceinline__ void cp16(unsigned smem_addr, const void* gptr) {
    asm volatile("cp.async.cg.shared.global [%0], [%1], 16;"
                 :: "r"(smem_addr), "l"(gptr) : "memory");
}

// mma.sync m16n8k8 tf32: D += A*B (accumulate in-place)
__device__ __forceinline__ void mma_tf32(float* c, const float* a, const float* b) {
    asm volatile(
        "mma.sync.aligned.m16n8k8.row.col.f32.tf32.tf32.f32 "
        "{%0,%1,%2,%3}, {%4,%5,%6,%7}, {%8,%9}, {%0,%1,%2,%3};"
        : "+f"(c[0]), "+f"(c[1]), "+f"(c[2]), "+f"(c[3])
        : "r"(__float_as_uint(a[0])), "r"(__float_as_uint(a[1])),
          "r"(__float_as_uint(a[2])), "r"(__float_as_uint(a[3])),
          "r"(__float_as_uint(b[0])), "r"(__float_as_uint(b[1])));
}

// ---- scratch (device globals: allocation-free) ----
__device__ __align__(16) float g_xt [Tz * Bz * Iz];
__device__ __align__(16) float g_xg [Tz * Bz * G4];
__device__ __align__(16) float g_h1r[Tz * Bz * Hz];    // layer0 h, tf32-rounded
__device__ __align__(16) float g_h2r[Tz * Bz * Hz];    // layer1 h, tf32-rounded
__device__ __align__(16) float g_h2 [Tz * Bz * Hz];    // layer1 h, full fp32 (FC)
__device__ __align__(16) float g_w0r[G4 * Iz];
__device__ __align__(16) float g_w1r[G4 * Hz];

// ---- software grid barrier (128 blocks, all co-resident: 1 block/SM) ----
__device__ unsigned g_bar_count = 0;
__device__ volatile unsigned g_bar_gen = 0;

__device__ __forceinline__ void grid_sync() {
    __syncthreads();
    if (threadIdx.x == 0) {
        __threadfence();
        unsigned gen = g_bar_gen;
        if (atomicAdd(&g_bar_count, 1u) == gridDim.x - 1u) {
            g_bar_count = 0;
            __threadfence();
            g_bar_gen = gen + 1u;
        } else {
            while (g_bar_gen == gen) { }
            __threadfence();
        }
    }
    __syncthreads();
}

// ---------------------------------------------------------------------------
// Transpose x: [B,T,I] -> time-major [T,B,I], tf32-rounded
// ---------------------------------------------------------------------------
__global__ void transpose_x(const float4* __restrict__ x, float4* __restrict__ xt) {
    int idx = blockIdx.x * blockDim.x + threadIdx.x;   // < 1048576
    int i4 = idx & 63;
    int m  = idx >> 6;
    int t  = m >> 5;
    int b  = m & 31;
    float4 v = x[(b * Tz + t) * (Iz / 4) + i4];
    v.x = t32(v.x); v.y = t32(v.y); v.z = t32(v.z); v.w = t32(v.w);
    xt[idx] = v;
}

__global__ void round_tf32_k(const float4* __restrict__ in, float4* __restrict__ out, int n4) {
    int i = blockIdx.x * blockDim.x + threadIdx.x;
    if (i < n4) {
        float4 v = in[i];
        v.x = t32(v.x); v.y = t32(v.y); v.z = t32(v.z); v.w = t32(v.w);
        out[i] = v;
    }
}

// ---------------------------------------------------------------------------
// TF32 tensor-core GEMM (TN) — R12 (passing). BM=BN=128, BK=32, 8 warps.
// ---------------------------------------------------------------------------
#define GST 36
#define TILE_F (128 * GST)

__global__ __launch_bounds__(256, 2)
void gemm_tf32(const float* __restrict__ A, const float* __restrict__ W,
               const float* __restrict__ b1, const float* __restrict__ b2,
               float* __restrict__ C, int M, int N, int K) {
    extern __shared__ float smg[];

    const int tid = threadIdx.x;
    const int lane = tid & 31;
    const int wid = tid >> 5;
    const int g = lane >> 2, tg = lane & 3;
    const int wm = wid & 1, wn = wid >> 1;
    const int m0 = blockIdx.y * 128, n0 = blockIdx.x * 128;

    unsigned smem_u32;
    asm("{ .reg .u64 t0; cvta.to.shared.u64 t0, %1; cvt.u32.u64 %0, t0; }"
        : "=r"(smem_u32) : "l"(smg));

    const int srow0 = tid >> 3, sc4 = tid & 7;
    const float* Abase = A + (size_t)m0 * K;
    const float* Wbase = W + (size_t)n0 * K;

    float acc[4][4][4];
#pragma unroll
    for (int mt = 0; mt < 4; mt++)
#pragma unroll
        for (int nt = 0; nt < 4; nt++)
#pragma unroll
            for (int i = 0; i < 4; i++) acc[mt][nt][i] = 0.0f;

    const int KT = K >> 5;

    auto issue = [&](int s, int kt) {
        unsigned sA = smem_u32 + (unsigned)(s * 2 * TILE_F) * 4u;
        unsigned sB = sA + (unsigned)TILE_F * 4u;
        const float* Ak = Abase + kt * 32;
        const float* Wk = Wbase + kt * 32;
#pragma unroll
        for (int i = 0; i < 4; i++) {
            int row = srow0 + 32 * i;
            unsigned doff = (unsigned)(row * GST + sc4 * 4) * 4u;
            cp16(sA + doff, Ak + (size_t)row * K + sc4 * 4);
            cp16(sB + doff, Wk + (size_t)row * K + sc4 * 4);
        }
    };

    issue(0, 0);
    asm volatile("cp.async.commit_group;" ::: "memory");
    issue(1, 1);
    asm volatile("cp.async.commit_group;" ::: "memory");

    for (int kt = 0; kt < KT; kt++) {
        asm volatile("cp.async.wait_group 1;" ::: "memory");
        __syncthreads();

        const int s = kt & 1;
        const float* sa = smg + s * 2 * TILE_F + (wm * 64) * GST;
        const float* sb = smg + s * 2 * TILE_F + TILE_F + (wn * 32) * GST;

#pragma unroll
        for (int ks = 0; ks < 4; ks++) {
            const int kk = ks * 8;
            float a[4][4], b[4][2];
#pragma unroll
            for (int mt = 0; mt < 4; mt++) {
                const float* ap = sa + (mt * 16) * GST + kk;
                a[mt][0] = ap[g * GST + tg];
                a[mt][1] = ap[(g + 8) * GST + tg];
                a[mt][2] = ap[g * GST + tg + 4];
                a[mt][3] = ap[(g + 8) * GST + tg + 4];
            }
#pragma unroll
            for (int nt = 0; nt < 4; nt++) {
                const float* bp = sb + (nt * 8) * GST + kk;
                b[nt][0] = bp[g * GST + tg];
                b[nt][1] = bp[g * GST + tg + 4];
            }
#pragma unroll
            for (int mt = 0; mt < 4; mt++)
#pragma unroll
                for (int nt = 0; nt < 4; nt++)
                    mma_tf32(acc[mt][nt], a[mt], b[nt]);
        }
        __syncthreads();
        if (kt + 2 < KT) issue(s, kt + 2);
        asm volatile("cp.async.commit_group;" ::: "memory");
    }

#pragma unroll
    for (int nt = 0; nt < 4; nt++) {
        int col = n0 + wn * 32 + nt * 8 + 2 * tg;
        float bia0 = b1[col]     + (b2 ? b2[col]     : 0.0f);
        float bia1 = b1[col + 1] + (b2 ? b2[col + 1] : 0.0f);
#pragma unroll
        for (int mt = 0; mt < 4; mt++) {
            int row = m0 + wm * 64 + mt * 16 + g;
            float2 v0 = make_float2(acc[mt][nt][0] + bia0, acc[mt][nt][1] + bia1);
            float2 v1 = make_float2(acc[mt][nt][2] + bia0, acc[mt][nt][3] + bia1);
            *(float2*)(C + (size_t)row * N + col) = v0;
            *(float2*)(C + (size_t)(row + 8) * N + col) = v1;
        }
    }
}

// ---------------------------------------------------------------------------
// SGEMM (TN) f32x2 — FC layer (full precision on the output path)
// ---------------------------------------------------------------------------
__global__ __launch_bounds__(256, 2)
void sgemm_fc(const float* __restrict__ A, const float* __restrict__ W,
              const float* __restrict__ b1,
              float* __restrict__ C, int M, int N, int K) {
    __shared__ __align__(16) float As[16][128];
    __shared__ __align__(16) float Bs[16][128];

    const int tid = threadIdx.x;
    const int ty = tid >> 4, tx = tid & 15;
    const int m0 = blockIdx.y * 128, n0 = blockIdx.x * 128;

    ull acc[4][8];
#pragma unroll
    for (int i = 0; i < 4; i++)
#pragma unroll
        for (int j = 0; j < 8; j++) acc[i][j] = 0ULL;

    const float* arow[2];
    int arr[2], acc4[2];
#pragma unroll
    for (int i = 0; i < 2; i++) {
        int item = tid + 256 * i;
        int r = item >> 2, c4 = item & 3;
        arr[i] = r; acc4[i] = c4;
        int m = m0 + r;
        int bb = m / TR, t = m - bb * TR;
        arow[i] = A + (long long)(t * Bz + bb) * K;
    }
    const float* wrow[2];
#pragma unroll
    for (int i = 0; i < 2; i++) wrow[i] = W + (long long)(n0 + arr[i]) * K;

    float4 va[2], vb[2];
#pragma unroll
    for (int i = 0; i < 2; i++) {
        va[i] = *(const float4*)(arow[i] + acc4[i] * 4);
        vb[i] = *(const float4*)(wrow[i] + acc4[i] * 4);
    }
#pragma unroll
    for (int i = 0; i < 2; i++) {
        int r = arr[i], c4 = acc4[i];
        As[c4 * 4 + 0][r] = va[i].x; As[c4 * 4 + 1][r] = va[i].y;
        As[c4 * 4 + 2][r] = va[i].z; As[c4 * 4 + 3][r] = va[i].w;
        Bs[c4 * 4 + 0][r] = vb[i].x; Bs[c4 * 4 + 1][r] = vb[i].y;
        Bs[c4 * 4 + 2][r] = vb[i].z; Bs[c4 * 4 + 3][r] = vb[i].w;
    }
    __syncthreads();

    const int KT = K >> 4;
    for (int kt = 0; kt < KT; kt++) {
        if (kt + 1 < KT) {
            int k0n = (kt + 1) << 4;
#pragma unroll
            for (int i = 0; i < 2; i++) {
                va[i] = *(const float4*)(arow[i] + k0n + acc4[i] * 4);
                vb[i] = *(const float4*)(wrow[i] + k0n + acc4[i] * 4);
            }
        }
#pragma unroll
        for (int k = 0; k < 16; k++) {
            ull a2[4];
#pragma unroll
            for (int mp = 0; mp < 4; mp++)
                a2[mp] = *(const ull*)&As[k][ty * 8 + mp * 2];
            float4 bv0 = *(const float4*)&Bs[k][tx * 8];
            float4 bv1 = *(const float4*)&Bs[k][tx * 8 + 4];
            ull bd[8];
            bd[0] = pack2(bv0.x, bv0.x); bd[1] = pack2(bv0.y, bv0.y);
            bd[2] = pack2(bv0.z, bv0.z); bd[3] = pack2(bv0.w, bv0.w);
            bd[4] = pack2(bv1.x, bv1.x); bd[5] = pack2(bv1.y, bv1.y);
            bd[6] = pack2(bv1.z, bv1.z); bd[7] = pack2(bv1.w, bv1.w);
#pragma unroll
            for (int mp = 0; mp < 4; mp++)
#pragma unroll
                for (int n = 0; n < 8; n++) fma2(acc[mp][n], a2[mp], bd[n]);
        }
        if (kt + 1 < KT) {
            __syncthreads();
#pragma unroll
            for (int i = 0; i < 2; i++) {
                int r = arr[i], c4 = acc4[i];
                As[c4 * 4 + 0][r] = va[i].x; As[c4 * 4 + 1][r] = va[i].y;
                As[c4 * 4 + 2][r] = va[i].z; As[c4 * 4 + 3][r] = va[i].w;
                Bs[c4 * 4 + 0][r] = vb[i].x; Bs[c4 * 4 + 1][r] = vb[i].y;
                Bs[c4 * 4 + 2][r] = vb[i].z; Bs[c4 * 4 + 3][r] = vb[i].w;
            }
            __syncthreads();
        }
    }

    float bb[8];
#pragma unroll
    for (int n = 0; n < 8; n++) bb[n] = b1[n0 + tx * 8 + n];
#pragma unroll
    for (int mp = 0; mp < 4; mp++) {
        float lo[8], hi[8];
#pragma unroll
        for (int n = 0; n < 8; n++) unpack2(acc[mp][n], lo[n], hi[n]);
        int row0 = m0 + ty * 8 + mp * 2;
        float* c0 = C + (long long)row0 * N + n0 + tx * 8;
        float* c1 = c0 + N;
        float o0[8], o1[8];
#pragma unroll
        for (int n = 0; n < 8; n++) { o0[n] = lo[n] + bb[n]; o1[n] = hi[n] + bb[n]; }
        *(float4*)(c0)     = make_float4(o0[0], o0[1], o0[2], o0[3]);
        *(float4*)(c0 + 4) = make_float4(o0[4], o0[5], o0[6], o0[7]);
        *(float4*)(c1)     = make_float4(o1[0], o1[1], o1[2], o1[3]);
        *(float4*)(c1 + 4) = make_float4(o1[4], o1[5], o1[6], o1[7]);
    }
}

// ---------------------------------------------------------------------------
// R14: tensor-core persistent LSTM recurrence, W register-resident.
// 128 blocks x 256 threads (8 warps = wm:2 gate-row tiles x wk:4 k-quarters).
// Roles swapped vs R13: A = W slice (32 gate-rows, m), B = h (32 batches, n).
// W A-fragments loaded ONCE into 128 regs/thread (tf32-rounded). Per step:
// h[t-1] staged as 2 k-halves (cp.async double buffer, HST2=516 conflict-free),
// per warp 128 HMMA + 256 LDS (4 independent acc chains), k-reduce over wk via
// gsm exchange, fused pointwise, write hr (tf32) + optional hf (fp32).
// ---------------------------------------------------------------------------
#define HST2 516     // h smem row stride (516%32==4 -> (4g+tg)%32 conflict-free)

__global__ __launch_bounds__(256, 1)
void lstm_rec_tc(const float* __restrict__ xg,    // [T][B][4H]
                 const float* __restrict__ Whh,   // [4H][H] fp32
                 float* __restrict__ hr,          // [T][B][H] tf32-rounded out
                 float* __restrict__ hf) {        // [T][B][H] fp32 out (nullable)
    extern __shared__ float sm[];
    float* hsm = sm;                         // [2][32][HST2]
    float* gsm = sm + 2 * 32 * HST2;         // [4][32][34]

    const int tid = threadIdx.x;
    const int lane = tid & 31, wid = tid >> 5;
    const int wm = wid & 1, wk = wid >> 1;   // wm: gate-row tile, wk: k-quarter
    const int g = lane >> 2, tg = lane & 3;
    const int j0 = blockIdx.x * 8;
    const int eu = tid & 7, eb = tid >> 3;   // epilogue role: (batch eb, unit eu)
    const int j = j0 + eu;

    unsigned hsm_u32;
    asm("{ .reg .u64 t0; cvta.to.shared.u64 t0, %1; cvt.u32.u64 %0, t0; }"
        : "=r"(hsm_u32) : "l"(hsm));

    // ---- W A-fragments -> registers (once per layer), tf32-rounded.
    // m = wm*16 + (g | g+8): gate = wm*2 (+1 for g+8 row), unit = g.
    float wa[2][16][4];
    {
        const float* r0 = Whh + (size_t)((wm * 2)     * Hz + j0 + g) * Hz;
        const float* r1 = Whh + (size_t)((wm * 2 + 1) * Hz + j0 + g) * Hz;
#pragma unroll
        for (int half = 0; half < 2; half++)
#pragma unroll
            for (int kt = 0; kt < 16; kt++) {
                int k = half * 512 + wk * 128 + kt * 8;
                wa[half][kt][0] = t32(__ldg(r0 + k + tg));
                wa[half][kt][1] = t32(__ldg(r1 + k + tg));
                wa[half][kt][2] = t32(__ldg(r0 + k + tg + 4));
                wa[half][kt][3] = t32(__ldg(r1 + k + tg + 4));
            }
    }

    // stage one k-half of h[t-1]: 32 rows x 512 floats = 4096 cp16, 16/thread
    auto stage = [&](int half, const float* hp) {
#pragma unroll
        for (int i = 0; i < 16; i++) {
            int idx = i * 256 + tid;
            int row = idx >> 7, ch = idx & 127;
            cp16(hsm_u32 + (unsigned)((half * 32 + row) * HST2 + ch * 4) * 4u,
                 hp + (size_t)row * Hz + half * 512 + ch * 4);
        }
        asm volatile("cp.async.commit_group;" ::: "memory");
    };

    float creg = 0.0f;   // c[eb][j] register-resident

    for (int t = 0; t < Tz; t++) {
        const float* xr = xg + (size_t)t * Bz * G4 + (size_t)eb * G4;
        float pi = __ldg(xr + j);
        float pf = __ldg(xr + Hz + j);
        float pg = __ldg(xr + 2 * Hz + j);
        float po = __ldg(xr + 3 * Hz + j);

        if (t > 0) {
            const float* hp = hr + (size_t)(t - 1) * Bz * Hz;
            stage(0, hp);
            stage(1, hp);

            float acc[4][4];
#pragma unroll
            for (int nt = 0; nt < 4; nt++)
#pragma unroll
                for (int i = 0; i < 4; i++) acc[nt][i] = 0.0f;

#pragma unroll
            for (int half = 0; half < 2; half++) {
                if (half == 0) asm volatile("cp.async.wait_group 1;" ::: "memory");
                else           asm volatile("cp.async.wait_group 0;" ::: "memory");
                __syncthreads();
                const float* hb = hsm + half * 32 * HST2 + wk * 128;
#pragma unroll
                for (int kt = 0; kt < 16; kt++) {
                    const int kc = kt * 8;
#pragma unroll
                    for (int nt = 0; nt < 4; nt++) {
                        float b[2];
                        const float* bp = hb + (nt * 8 + g) * HST2 + kc;
                        b[0] = bp[tg];
                        b[1] = bp[tg + 4];
                        mma_tf32(acc[nt], wa[half][kt], b);
                    }
                }
            }

            // publish wk-partials: gsm[wk][gate-row][batch], stride 34
            float* gp = gsm + wk * (32 * 34);
#pragma unroll
            for (int nt = 0; nt < 4; nt++) {
                int bcol = nt * 8 + 2 * tg;
                *(float2*)(gp + (wm * 16 + g) * 34 + bcol) =
                    make_float2(acc[nt][0], acc[nt][1]);
                *(float2*)(gp + (wm * 16 + 8 + g) * 34 + bcol) =
                    make_float2(acc[nt][2], acc[nt][3]);
            }
            __syncthreads();

            // gather gates for (eb, eu): row = gate*8+eu, sum 4 wk partials
#pragma unroll
            for (int gt = 0; gt < 4; gt++) {
                int row = gt * 8 + eu;
                float s = gsm[row * 34 + eb]
                        + gsm[1 * 32 * 34 + row * 34 + eb]
                        + gsm[2 * 32 * 34 + row * 34 + eb]
                        + gsm[3 * 32 * 34 + row * 34 + eb];
                if      (gt == 0) pi += s;
                else if (gt == 1) pf += s;
                else if (gt == 2) pg += s;
                else              po += s;
            }
        }

        float si = sig_f(pi);
        float sf = sig_f(pf);
        float so = sig_f(po);
        creg = sf * creg + si * tanh_f(pg);
        float hn = so * tanh_f(creg);
        size_t oidx = (size_t)t * Bz * Hz + (size_t)eb * Hz + j;
        if (hf) hf[oidx] = hn;
        hr[oidx] = t32(hn);

        grid_sync();
    }
}

// ---------------------------------------------------------------------------
extern "C" void kernel_launch(void* const* d_in, const int* in_sizes, int n_in,
                              void* d_out, int out_size) {
    (void)in_sizes; (void)n_in; (void)out_size;
    const float* x     = (const float*)d_in[0];
    const float* W_ih0 = (const float*)d_in[1];
    const float* W_hh0 = (const float*)d_in[2];
    const float* b_ih0 = (const float*)d_in[3];
    const float* b_hh0 = (const float*)d_in[4];
    const float* W_ih1 = (const float*)d_in[5];
    const float* W_hh1 = (const float*)d_in[6];
    const float* b_ih1 = (const float*)d_in[7];
    const float* b_hh1 = (const float*)d_in[8];
    const float* W_fc  = (const float*)d_in[9];
    const float* b_fc  = (const float*)d_in[10];
    float* out = (float*)d_out;

    float *xt, *xgp, *h1r, *h2r, *h2, *w0r, *w1r;
    cudaGetSymbolAddress((void**)&xt,  g_xt);
    cudaGetSymbolAddress((void**)&xgp, g_xg);
    cudaGetSymbolAddress((void**)&h1r, g_h1r);
    cudaGetSymbolAddress((void**)&h2r, g_h2r);
    cudaGetSymbolAddress((void**)&h2,  g_h2);
    cudaGetSymbolAddress((void**)&w0r, g_w0r);
    cudaGetSymbolAddress((void**)&w1r, g_w1r);

    const int REC_SMEM  = (2 * 32 * HST2 + 4 * 32 * 34) * (int)sizeof(float); // 149504B
    const int GEMM_SMEM = 2 * 2 * TILE_F * (int)sizeof(float);                // 73728B
    cudaFuncSetAttribute(lstm_rec_tc,
                         cudaFuncAttributeMaxDynamicSharedMemorySize, REC_SMEM);
    cudaFuncSetAttribute(gemm_tf32,
                         cudaFuncAttributeMaxDynamicSharedMemorySize, GEMM_SMEM);

    // x -> time-major (tf32); round input-GEMM weights
    transpose_x<<<4096, 256>>>((const float4*)x, (float4*)xt);
    round_tf32_k<<<(G4 * Iz / 4 + 255) / 256, 256>>>((const float4*)W_ih0, (float4*)w0r, G4 * Iz / 4);
    round_tf32_k<<<(G4 * Hz / 4 + 255) / 256, 256>>>((const float4*)W_ih1, (float4*)w1r, G4 * Hz / 4);

    // layer 0: tf32 input GEMM + tensor-core recurrence (writes h1r tf32)
    gemm_tf32<<<dim3(G4 / 128, (Tz * Bz) / 128), 256, GEMM_SMEM>>>(
        xt, w0r, b_ih0, b_hh0, xgp, Tz * Bz, G4, Iz);
    lstm_rec_tc<<<128, 256, REC_SMEM>>>(xgp, W_hh0, h1r, nullptr);

    // layer 1: tf32 input GEMM (A = h1r, already rounded) + recurrence
    gemm_tf32<<<dim3(G4 / 128, (Tz * Bz) / 128), 256, GEMM_SMEM>>>(
        h1r, w1r, b_ih1, b_hh1, xgp, Tz * Bz, G4, Hz);
    lstm_rec_tc<<<128, 256, REC_SMEM>>>(xgp, W_hh1, h2r, h2);

    // FC over truncated sequence (full fp32): out[b,t,o], m = b*500 + t
    sgemm_fc<<<dim3(Oz / 128, (Bz * TR) / 128), 256>>>(h2, W_fc, b_fc,
                                                       out, Bz * TR, Oz, Hz);
}